// round 12
// baseline (speedup 1.0000x reference)
#include <cuda_runtime.h>
#include <cuda_fp16.h>

// FakeReviewGNN: 2-layer GCN, N=100000, 7 -> 64 -> 32 -> 2.
// CSR-free scatter pipeline, both scatters fp16; transform on tensor cores:
//   k_count     : dst histogram (cnt pre-zeroed / reset by k_final)
//   k_prep      : dinv = rsqrt(cnt+1); xdh = x*dinv as 8 halves; ph init = xdh
//   k_scatter16h: ph[dst] += xdh[src]          (1 x red.v4.f16x2 / edge)
//   k_transform : HMMA, 256 nodes/block, C-frag -> A-frag in regs
//   k_scatter32h: s2h[dst] += g2h[src]         (1 edge/thread, 4 reds)
//   k_final     : h2 = relu(dinv*s2+b2); log_softmax(h2@Wc+bc); reset cnt

#define MAXN 100000
#define F1 64
#define F2 32

__device__ int   d_cnt [MAXN];          // zero-init; k_final resets after use
__device__ float d_dinv[MAXN];
__device__ __align__(128) __half d_xdh[MAXN * 8];
__device__ __align__(128) __half d_ph [MAXN * 8];
__device__ __align__(128) __half d_g2h[MAXN * F2];
__device__ __align__(128) __half d_s2h[MAXN * F2];

__device__ __forceinline__ void red_add_v4h2(uint4* addr, uint4 v) {
    asm volatile("red.global.add.noftz.v4.f16x2 [%0], {%1, %2, %3, %4};"
                 :: "l"(addr), "r"(v.x), "r"(v.y), "r"(v.z), "r"(v.w)
                 : "memory");
}

__device__ __forceinline__ unsigned smem_u32(const void* p) {
    return (unsigned)__cvta_generic_to_shared(p);
}

// ---- histogram (cnt assumed zero on entry) ---------------------------------

__global__ void k_count_v4(const int4* __restrict__ dst4, int E4) {
    int i = blockIdx.x * blockDim.x + threadIdx.x;
    if (i >= E4) return;
    int4 d = dst4[i];
    atomicAdd(&d_cnt[d.x], 1);
    atomicAdd(&d_cnt[d.y], 1);
    atomicAdd(&d_cnt[d.z], 1);
    atomicAdd(&d_cnt[d.w], 1);
}

__global__ void k_count_sc(const int* __restrict__ dst, int E) {
    int i = blockIdx.x * blockDim.x + threadIdx.x;
    if (i < E) atomicAdd(&d_cnt[dst[i]], 1);
}

// ---- prep: dinv, xdh = x*dinv as fp16 (pad 7->8), ph init = xdh ------------

__global__ void k_prep(const float* __restrict__ x, int n) {
    int i = blockIdx.x * blockDim.x + threadIdx.x;
    if (i >= n) return;
    float dv = rsqrtf((float)(d_cnt[i] + 1));   // +1 self loop
    d_dinv[i] = dv;
    const float* xi = x + (long long)i * 7;
    __half2 h0 = __floats2half2_rn(xi[0] * dv, xi[1] * dv);
    __half2 h1 = __floats2half2_rn(xi[2] * dv, xi[3] * dv);
    __half2 h2 = __floats2half2_rn(xi[4] * dv, xi[5] * dv);
    __half2 h3 = __floats2half2_rn(xi[6] * dv, 0.0f);
    uint4 v;
    v.x = *reinterpret_cast<unsigned*>(&h0);
    v.y = *reinterpret_cast<unsigned*>(&h1);
    v.z = *reinterpret_cast<unsigned*>(&h2);
    v.w = *reinterpret_cast<unsigned*>(&h3);
    reinterpret_cast<uint4*>(d_xdh)[i] = v;
    reinterpret_cast<uint4*>(d_ph )[i] = v;
}

// ---- layer-1 scatter: ph[dst] += xdh[src], 1 red.v4.f16x2 / edge -----------

__global__ void k_scatter16h(const int* __restrict__ src,
                             const int* __restrict__ dst, int E) {
    int e = blockIdx.x * blockDim.x + threadIdx.x;
    if (e >= E) return;
    int u = src[e], v = dst[e];
    uint4 val = reinterpret_cast<const uint4*>(d_xdh)[u];
    red_add_v4h2(&reinterpret_cast<uint4*>(d_ph)[v], val);
}

// ---- tensor-core transform: 16 nodes/warp, 256 nodes/block (512 thr) -------

__global__ void __launch_bounds__(512) k_transform(const float* __restrict__ W1,
                                                   const float* __restrict__ b1,
                                                   const float* __restrict__ W2,
                                                   int n) {
    __shared__ __half W1h[8][F1];        // k-padded fp16 W1, 1 KB
    __shared__ __half W2h[F1][F2];       // fp16 W2, 4 KB
    __shared__ float  b1s[F1];
    __shared__ __half ph_s[256][8];      // 4 KB
    __shared__ float  dinv_s[256];

    int tid = threadIdx.x;
    for (int i = tid; i < 8 * F1; i += 512) {
        int k = i >> 6, c = i & 63;
        W1h[k][c] = __float2half((k < 7) ? W1[k * F1 + c] : 0.0f);
    }
    for (int i = tid; i < F1 * F2; i += 512)
        W2h[i >> 5][i & 31] = __float2half(W2[i]);
    if (tid < F1) b1s[tid] = b1[tid];

    int blockbase = blockIdx.x * 256;
    if (tid < 256) {
        int node = blockbase + tid; if (node >= n) node = n - 1;
        *reinterpret_cast<uint4*>(&ph_s[tid][0]) =
            reinterpret_cast<const uint4*>(d_ph)[node];
        dinv_s[tid] = d_dinv[node];
    }
    __syncthreads();

    int warp = tid >> 5;
    int lane = tid & 31;
    int r0   = warp * 16;                // this warp's 16 node rows

    // ---- phase 1: C1[16x64] = P[16x8] @ W1h[8x64], 8 x mma.m16n8k8 ----
    unsigned a0, a1;
    {
        unsigned addr = smem_u32(&ph_s[r0 + (lane & 15)][0]);
        asm volatile("ldmatrix.sync.aligned.m8n8.x2.shared.b16 {%0,%1}, [%2];"
                     : "=r"(a0), "=r"(a1) : "r"(addr));
    }
    unsigned bw1[8];
    {
        int k  = lane & 7;
        int t4 = (lane >> 3) & 3;
        unsigned ad0 = smem_u32(&W1h[k][t4 * 8]);
        unsigned ad1 = smem_u32(&W1h[k][32 + t4 * 8]);
        asm volatile("ldmatrix.sync.aligned.m8n8.x4.trans.shared.b16 {%0,%1,%2,%3}, [%4];"
                     : "=r"(bw1[0]), "=r"(bw1[1]), "=r"(bw1[2]), "=r"(bw1[3])
                     : "r"(ad0));
        asm volatile("ldmatrix.sync.aligned.m8n8.x4.trans.shared.b16 {%0,%1,%2,%3}, [%4];"
                     : "=r"(bw1[4]), "=r"(bw1[5]), "=r"(bw1[6]), "=r"(bw1[7])
                     : "r"(ad1));
    }

    float c1[8][4];
    #pragma unroll
    for (int nn = 0; nn < 8; nn++) {
        c1[nn][0] = c1[nn][1] = c1[nn][2] = c1[nn][3] = 0.0f;
        asm volatile(
            "mma.sync.aligned.m16n8k8.row.col.f32.f16.f16.f32 "
            "{%0,%1,%2,%3}, {%4,%5}, {%6}, {%0,%1,%2,%3};"
            : "+f"(c1[nn][0]), "+f"(c1[nn][1]), "+f"(c1[nn][2]), "+f"(c1[nn][3])
            : "r"(a0), "r"(a1), "r"(bw1[nn]));
    }

    // ---- epilogue 1: h1 = relu(dv*c1 + b1), pack to phase-2 A fragments ----
    int g  = lane >> 2;
    int tc = (lane & 3) * 2;
    float dv0 = dinv_s[r0 + g];
    float dv1 = dinv_s[r0 + 8 + g];

    unsigned a2f[4][4];                  // [kk][a0,a1,a2,a3]
    #pragma unroll
    for (int nn = 0; nn < 8; nn++) {
        int col = nn * 8 + tc;
        float h0 = fmaxf(dv0 * c1[nn][0] + b1s[col],     0.0f);
        float h1 = fmaxf(dv0 * c1[nn][1] + b1s[col + 1], 0.0f);
        float h2 = fmaxf(dv1 * c1[nn][2] + b1s[col],     0.0f);
        float h3 = fmaxf(dv1 * c1[nn][3] + b1s[col + 1], 0.0f);
        __half2 p01 = __floats2half2_rn(h0, h1);
        __half2 p23 = __floats2half2_rn(h2, h3);
        int kk = nn >> 1, hi = nn & 1;
        a2f[kk][hi * 2]     = *reinterpret_cast<unsigned*>(&p01);
        a2f[kk][hi * 2 + 1] = *reinterpret_cast<unsigned*>(&p23);
    }

    // ---- phase 2: C2[16x32] = H1[16x64] @ W2h[64x32], 16 x mma.m16n8k16 ----
    float c2[4][4];
    #pragma unroll
    for (int nn = 0; nn < 4; nn++)
        c2[nn][0] = c2[nn][1] = c2[nn][2] = c2[nn][3] = 0.0f;

    #pragma unroll
    for (int kk = 0; kk < 4; kk++) {
        #pragma unroll
        for (int nn = 0; nn < 4; nn++) {
            unsigned b0, b1r;
            unsigned addr = smem_u32(&W2h[kk * 16 + (lane & 15)][nn * 8]);
            asm volatile("ldmatrix.sync.aligned.m8n8.x2.trans.shared.b16 {%0,%1}, [%2];"
                         : "=r"(b0), "=r"(b1r) : "r"(addr));
            asm volatile(
                "mma.sync.aligned.m16n8k16.row.col.f32.f16.f16.f32 "
                "{%0,%1,%2,%3}, {%4,%5,%6,%7}, {%8,%9}, {%0,%1,%2,%3};"
                : "+f"(c2[nn][0]), "+f"(c2[nn][1]), "+f"(c2[nn][2]), "+f"(c2[nn][3])
                : "r"(a2f[kk][0]), "r"(a2f[kk][1]), "r"(a2f[kk][2]), "r"(a2f[kk][3]),
                  "r"(b0), "r"(b1r));
        }
    }

    // ---- epilogue 2: g2 = c2 * dinv -> fp16 store (g2h and s2h) ------------
    int node0 = blockbase + r0 + g;
    int node1 = node0 + 8;
    #pragma unroll
    for (int nn = 0; nn < 4; nn++) {
        int col = nn * 8 + tc;
        __half2 v0 = __floats2half2_rn(c2[nn][0] * dv0, c2[nn][1] * dv0);
        __half2 v1 = __floats2half2_rn(c2[nn][2] * dv1, c2[nn][3] * dv1);
        if (node0 < n) {
            *reinterpret_cast<__half2*>(&d_g2h[(node0 << 5) + col]) = v0;
            *reinterpret_cast<__half2*>(&d_s2h[(node0 << 5) + col]) = v0;
        }
        if (node1 < n) {
            *reinterpret_cast<__half2*>(&d_g2h[(node1 << 5) + col]) = v1;
            *reinterpret_cast<__half2*>(&d_s2h[(node1 << 5) + col]) = v1;
        }
    }
}

// ---- layer-2 scatter: one edge/thread, 4 gathers + 4 reds ------------------

__global__ void k_scatter32h(const int* __restrict__ src,
                             const int* __restrict__ dst, int E) {
    int e = blockIdx.x * blockDim.x + threadIdx.x;
    if (e >= E) return;
    int u = src[e], v = dst[e];
    const uint4* g = reinterpret_cast<const uint4*>(d_g2h) + ((long long)u << 2);
    uint4*       s = reinterpret_cast<uint4*>(d_s2h)       + ((long long)v << 2);
    uint4 v0 = __ldg(&g[0]);
    uint4 v1 = __ldg(&g[1]);
    uint4 v2 = __ldg(&g[2]);
    uint4 v3 = __ldg(&g[3]);
    red_add_v4h2(&s[0], v0);
    red_add_v4h2(&s[1], v1);
    red_add_v4h2(&s[2], v2);
    red_add_v4h2(&s[3], v3);
}

// ---- final: relu + classifier + log_softmax + cnt reset (thread/node) ------

__global__ void k_final(const float* __restrict__ b2,
                        const float* __restrict__ Wc,
                        const float* __restrict__ bc,
                        float* __restrict__ out, int n) {
    int node = blockIdx.x * blockDim.x + threadIdx.x;
    if (node >= n) return;

    float dv = d_dinv[node];
    const uint4* s4 = reinterpret_cast<const uint4*>(d_s2h) + (long long)node * 4;
    float l0 = bc[0], l1 = bc[1];

    #pragma unroll
    for (int j = 0; j < 4; j++) {
        uint4 q = s4[j];
        unsigned w[4] = {q.x, q.y, q.z, q.w};
        #pragma unroll
        for (int t = 0; t < 4; t++) {
            float2 v = __half22float2(*reinterpret_cast<const __half2*>(&w[t]));
            int k = j * 8 + t * 2;
            float h0 = fmaxf(dv * v.x + b2[k],     0.0f);
            float h1 = fmaxf(dv * v.y + b2[k + 1], 0.0f);
            l0 += h0 * Wc[k * 2]     + h1 * Wc[k * 2 + 2];
            l1 += h0 * Wc[k * 2 + 1] + h1 * Wc[k * 2 + 3];
        }
    }

    float m   = fmaxf(l0, l1);
    float lse = m + logf(expf(l0 - m) + expf(l1 - m));
    out[(long long)node * 2]     = l0 - lse;
    out[(long long)node * 2 + 1] = l1 - lse;
    d_cnt[node] = 0;   // reset histogram for next replay (deterministic)
}

// ---- launch ----------------------------------------------------------------

extern "C" void kernel_launch(void* const* d_in, const int* in_sizes, int n_in,
                              void* d_out, int out_size) {
    const float* x  = (const float*)d_in[0];
    const int*   ei = (const int*)  d_in[1];
    const float* W1 = (const float*)d_in[2];
    const float* b1 = (const float*)d_in[3];
    const float* W2 = (const float*)d_in[4];
    const float* b2 = (const float*)d_in[5];
    const float* Wc = (const float*)d_in[6];
    const float* bc = (const float*)d_in[7];
    float* out = (float*)d_out;

    int n = in_sizes[0] / 7;     // 100000
    int E = in_sizes[1] / 2;     // 1600000
    const int* src = ei;
    const int* dst = ei + E;

    const int T = 256;

    bool vec_ok = (E % 4 == 0) && ((((unsigned long long)dst) & 15ull) == 0);
    if (vec_ok) {
        int E4 = E / 4;
        k_count_v4<<<(E4 + T - 1) / T, T>>>((const int4*)dst, E4);
    } else {
        k_count_sc<<<(E + T - 1) / T, T>>>(dst, E);
    }

    k_prep<<<(n + T - 1) / T, T>>>(x, n);

    k_scatter16h<<<(E + T - 1) / T, T>>>(src, dst, E);

    k_transform<<<(n + 255) / 256, 512>>>(W1, b1, W2, n);

    k_scatter32h<<<(E + T - 1) / T, T>>>(src, dst, E);

    k_final<<<(n + T - 1) / T, T>>>(b2, Wc, bc, out, n);
}

// round 13
// speedup vs baseline: 1.2724x; 1.2724x over previous
#include <cuda_runtime.h>
#include <cuda_fp16.h>

// FakeReviewGNN: 2-layer GCN, N=100000, 7 -> 64 -> 32 -> 2.
// CSR-free scatter pipeline, both scatters fp16; transform on tensor cores:
//   k_count     : dst histogram (cnt pre-zeroed / reset by k_final)
//   k_prep      : dinv = rsqrt(cnt+1); xdh = x*dinv as 8 halves; ph init = xdh
//   k_scatter16h: ph[dst] += xdh[src]          (1 x red.v4.f16x2 / edge)
//   k_transform : HMMA, 256 nodes/block / 512 thr, C-frag -> A-frag in regs
//   k_scatter32h: s2h[dst] += g2h[src]         (4 threads/edge, coalesced)
//   k_final     : h2 = relu(dinv*s2+b2); log_softmax(h2@Wc+bc); reset cnt

#define MAXN 100000
#define F1 64
#define F2 32

__device__ int   d_cnt [MAXN];          // zero-init; k_final resets after use
__device__ float d_dinv[MAXN];
__device__ __align__(128) __half d_xdh[MAXN * 8];
__device__ __align__(128) __half d_ph [MAXN * 8];
__device__ __align__(128) __half d_g2h[MAXN * F2];
__device__ __align__(128) __half d_s2h[MAXN * F2];

__device__ __forceinline__ void red_add_v4h2(uint4* addr, uint4 v) {
    asm volatile("red.global.add.noftz.v4.f16x2 [%0], {%1, %2, %3, %4};"
                 :: "l"(addr), "r"(v.x), "r"(v.y), "r"(v.z), "r"(v.w)
                 : "memory");
}

__device__ __forceinline__ unsigned smem_u32(const void* p) {
    return (unsigned)__cvta_generic_to_shared(p);
}

// ---- histogram (cnt assumed zero on entry) ---------------------------------

__global__ void k_count_v4(const int4* __restrict__ dst4, int E4) {
    int i = blockIdx.x * blockDim.x + threadIdx.x;
    if (i >= E4) return;
    int4 d = dst4[i];
    atomicAdd(&d_cnt[d.x], 1);
    atomicAdd(&d_cnt[d.y], 1);
    atomicAdd(&d_cnt[d.z], 1);
    atomicAdd(&d_cnt[d.w], 1);
}

__global__ void k_count_sc(const int* __restrict__ dst, int E) {
    int i = blockIdx.x * blockDim.x + threadIdx.x;
    if (i < E) atomicAdd(&d_cnt[dst[i]], 1);
}

// ---- prep: dinv, xdh = x*dinv as fp16 (pad 7->8), ph init = xdh ------------

__global__ void k_prep(const float* __restrict__ x, int n) {
    int i = blockIdx.x * blockDim.x + threadIdx.x;
    if (i >= n) return;
    float dv = rsqrtf((float)(d_cnt[i] + 1));   // +1 self loop
    d_dinv[i] = dv;
    const float* xi = x + (long long)i * 7;
    __half2 h0 = __floats2half2_rn(xi[0] * dv, xi[1] * dv);
    __half2 h1 = __floats2half2_rn(xi[2] * dv, xi[3] * dv);
    __half2 h2 = __floats2half2_rn(xi[4] * dv, xi[5] * dv);
    __half2 h3 = __floats2half2_rn(xi[6] * dv, 0.0f);
    uint4 v;
    v.x = *reinterpret_cast<unsigned*>(&h0);
    v.y = *reinterpret_cast<unsigned*>(&h1);
    v.z = *reinterpret_cast<unsigned*>(&h2);
    v.w = *reinterpret_cast<unsigned*>(&h3);
    reinterpret_cast<uint4*>(d_xdh)[i] = v;
    reinterpret_cast<uint4*>(d_ph )[i] = v;
}

// ---- layer-1 scatter: ph[dst] += xdh[src], 1 red.v4.f16x2 / edge -----------

__global__ void k_scatter16h(const int* __restrict__ src,
                             const int* __restrict__ dst, int E) {
    int e = blockIdx.x * blockDim.x + threadIdx.x;
    if (e >= E) return;
    int u = src[e], v = dst[e];
    uint4 val = reinterpret_cast<const uint4*>(d_xdh)[u];
    red_add_v4h2(&reinterpret_cast<uint4*>(d_ph)[v], val);
}

// ---- tensor-core transform: 16 nodes/warp, 256 nodes/block (512 thr) -------

__global__ void __launch_bounds__(512) k_transform(const float* __restrict__ W1,
                                                   const float* __restrict__ b1,
                                                   const float* __restrict__ W2,
                                                   int n) {
    __shared__ __half W1h[8][F1];        // k-padded fp16 W1, 1 KB
    __shared__ __half W2h[F1][F2];       // fp16 W2, 4 KB
    __shared__ float  b1s[F1];
    __shared__ __half ph_s[256][8];      // 4 KB
    __shared__ float  dinv_s[256];

    int tid = threadIdx.x;
    for (int i = tid; i < 8 * F1; i += 512) {
        int k = i >> 6, c = i & 63;
        W1h[k][c] = __float2half((k < 7) ? W1[k * F1 + c] : 0.0f);
    }
    for (int i = tid; i < F1 * F2; i += 512)
        W2h[i >> 5][i & 31] = __float2half(W2[i]);
    if (tid < F1) b1s[tid] = b1[tid];

    int blockbase = blockIdx.x * 256;
    if (tid < 256) {
        int node = blockbase + tid; if (node >= n) node = n - 1;
        *reinterpret_cast<uint4*>(&ph_s[tid][0]) =
            reinterpret_cast<const uint4*>(d_ph)[node];
        dinv_s[tid] = d_dinv[node];
    }
    __syncthreads();

    int warp = tid >> 5;
    int lane = tid & 31;
    int r0   = warp * 16;                // this warp's 16 node rows

    // ---- phase 1: C1[16x64] = P[16x8] @ W1h[8x64], 8 x mma.m16n8k8 ----
    unsigned a0, a1;
    {
        unsigned addr = smem_u32(&ph_s[r0 + (lane & 15)][0]);
        asm volatile("ldmatrix.sync.aligned.m8n8.x2.shared.b16 {%0,%1}, [%2];"
                     : "=r"(a0), "=r"(a1) : "r"(addr));
    }
    unsigned bw1[8];
    {
        int k  = lane & 7;
        int t4 = (lane >> 3) & 3;
        unsigned ad0 = smem_u32(&W1h[k][t4 * 8]);
        unsigned ad1 = smem_u32(&W1h[k][32 + t4 * 8]);
        asm volatile("ldmatrix.sync.aligned.m8n8.x4.trans.shared.b16 {%0,%1,%2,%3}, [%4];"
                     : "=r"(bw1[0]), "=r"(bw1[1]), "=r"(bw1[2]), "=r"(bw1[3])
                     : "r"(ad0));
        asm volatile("ldmatrix.sync.aligned.m8n8.x4.trans.shared.b16 {%0,%1,%2,%3}, [%4];"
                     : "=r"(bw1[4]), "=r"(bw1[5]), "=r"(bw1[6]), "=r"(bw1[7])
                     : "r"(ad1));
    }

    float c1[8][4];
    #pragma unroll
    for (int nn = 0; nn < 8; nn++) {
        c1[nn][0] = c1[nn][1] = c1[nn][2] = c1[nn][3] = 0.0f;
        asm volatile(
            "mma.sync.aligned.m16n8k8.row.col.f32.f16.f16.f32 "
            "{%0,%1,%2,%3}, {%4,%5}, {%6}, {%0,%1,%2,%3};"
            : "+f"(c1[nn][0]), "+f"(c1[nn][1]), "+f"(c1[nn][2]), "+f"(c1[nn][3])
            : "r"(a0), "r"(a1), "r"(bw1[nn]));
    }

    // ---- epilogue 1: h1 = relu(dv*c1 + b1), pack to phase-2 A fragments ----
    int g  = lane >> 2;
    int tc = (lane & 3) * 2;
    float dv0 = dinv_s[r0 + g];
    float dv1 = dinv_s[r0 + 8 + g];

    unsigned a2f[4][4];                  // [kk][a0,a1,a2,a3]
    #pragma unroll
    for (int nn = 0; nn < 8; nn++) {
        int col = nn * 8 + tc;
        float h0 = fmaxf(dv0 * c1[nn][0] + b1s[col],     0.0f);
        float h1 = fmaxf(dv0 * c1[nn][1] + b1s[col + 1], 0.0f);
        float h2 = fmaxf(dv1 * c1[nn][2] + b1s[col],     0.0f);
        float h3 = fmaxf(dv1 * c1[nn][3] + b1s[col + 1], 0.0f);
        __half2 p01 = __floats2half2_rn(h0, h1);
        __half2 p23 = __floats2half2_rn(h2, h3);
        int kk = nn >> 1, hi = nn & 1;
        a2f[kk][hi * 2]     = *reinterpret_cast<unsigned*>(&p01);
        a2f[kk][hi * 2 + 1] = *reinterpret_cast<unsigned*>(&p23);
    }

    // ---- phase 2: C2[16x32] = H1[16x64] @ W2h[64x32], 16 x mma.m16n8k16 ----
    float c2[4][4];
    #pragma unroll
    for (int nn = 0; nn < 4; nn++)
        c2[nn][0] = c2[nn][1] = c2[nn][2] = c2[nn][3] = 0.0f;

    #pragma unroll
    for (int kk = 0; kk < 4; kk++) {
        #pragma unroll
        for (int nn = 0; nn < 4; nn++) {
            unsigned b0, b1r;
            unsigned addr = smem_u32(&W2h[kk * 16 + (lane & 15)][nn * 8]);
            asm volatile("ldmatrix.sync.aligned.m8n8.x2.trans.shared.b16 {%0,%1}, [%2];"
                         : "=r"(b0), "=r"(b1r) : "r"(addr));
            asm volatile(
                "mma.sync.aligned.m16n8k16.row.col.f32.f16.f16.f32 "
                "{%0,%1,%2,%3}, {%4,%5,%6,%7}, {%8,%9}, {%0,%1,%2,%3};"
                : "+f"(c2[nn][0]), "+f"(c2[nn][1]), "+f"(c2[nn][2]), "+f"(c2[nn][3])
                : "r"(a2f[kk][0]), "r"(a2f[kk][1]), "r"(a2f[kk][2]), "r"(a2f[kk][3]),
                  "r"(b0), "r"(b1r));
        }
    }

    // ---- epilogue 2: g2 = c2 * dinv -> fp16 store (g2h and s2h) ------------
    int node0 = blockbase + r0 + g;
    int node1 = node0 + 8;
    #pragma unroll
    for (int nn = 0; nn < 4; nn++) {
        int col = nn * 8 + tc;
        __half2 v0 = __floats2half2_rn(c2[nn][0] * dv0, c2[nn][1] * dv0);
        __half2 v1 = __floats2half2_rn(c2[nn][2] * dv1, c2[nn][3] * dv1);
        if (node0 < n) {
            *reinterpret_cast<__half2*>(&d_g2h[(node0 << 5) + col]) = v0;
            *reinterpret_cast<__half2*>(&d_s2h[(node0 << 5) + col]) = v0;
        }
        if (node1 < n) {
            *reinterpret_cast<__half2*>(&d_g2h[(node1 << 5) + col]) = v1;
            *reinterpret_cast<__half2*>(&d_s2h[(node1 << 5) + col]) = v1;
        }
    }
}

// ---- layer-2 scatter: 4 threads/edge (coalesced), 4 red.v4.f16x2 / edge ----

__global__ void k_scatter32h(const int* __restrict__ src,
                             const int* __restrict__ dst, int E) {
    long long idx = (long long)blockIdx.x * blockDim.x + threadIdx.x;
    int e = (int)(idx >> 2);
    int c = (int)(idx & 3);
    if (e >= E) return;
    int u = src[e], v = dst[e];
    uint4 val = reinterpret_cast<const uint4*>(d_g2h)[(long long)u * 4 + c];
    red_add_v4h2(&reinterpret_cast<uint4*>(d_s2h)[(long long)v * 4 + c], val);
}

// ---- final: relu + classifier + log_softmax + cnt reset (thread/node) ------

__global__ void k_final(const float* __restrict__ b2,
                        const float* __restrict__ Wc,
                        const float* __restrict__ bc,
                        float* __restrict__ out, int n) {
    int node = blockIdx.x * blockDim.x + threadIdx.x;
    if (node >= n) return;

    float dv = d_dinv[node];
    const uint4* s4 = reinterpret_cast<const uint4*>(d_s2h) + (long long)node * 4;
    float l0 = bc[0], l1 = bc[1];

    #pragma unroll
    for (int j = 0; j < 4; j++) {
        uint4 q = s4[j];
        unsigned w[4] = {q.x, q.y, q.z, q.w};
        #pragma unroll
        for (int t = 0; t < 4; t++) {
            float2 v = __half22float2(*reinterpret_cast<const __half2*>(&w[t]));
            int k = j * 8 + t * 2;
            float h0 = fmaxf(dv * v.x + b2[k],     0.0f);
            float h1 = fmaxf(dv * v.y + b2[k + 1], 0.0f);
            l0 += h0 * Wc[k * 2]     + h1 * Wc[k * 2 + 2];
            l1 += h0 * Wc[k * 2 + 1] + h1 * Wc[k * 2 + 3];
        }
    }

    float m   = fmaxf(l0, l1);
    float lse = m + logf(expf(l0 - m) + expf(l1 - m));
    out[(long long)node * 2]     = l0 - lse;
    out[(long long)node * 2 + 1] = l1 - lse;
    d_cnt[node] = 0;   // reset histogram for next replay (deterministic)
}

// ---- launch ----------------------------------------------------------------

extern "C" void kernel_launch(void* const* d_in, const int* in_sizes, int n_in,
                              void* d_out, int out_size) {
    const float* x  = (const float*)d_in[0];
    const int*   ei = (const int*)  d_in[1];
    const float* W1 = (const float*)d_in[2];
    const float* b1 = (const float*)d_in[3];
    const float* W2 = (const float*)d_in[4];
    const float* b2 = (const float*)d_in[5];
    const float* Wc = (const float*)d_in[6];
    const float* bc = (const float*)d_in[7];
    float* out = (float*)d_out;

    int n = in_sizes[0] / 7;     // 100000
    int E = in_sizes[1] / 2;     // 1600000
    const int* src = ei;
    const int* dst = ei + E;

    const int T = 256;

    bool vec_ok = (E % 4 == 0) && ((((unsigned long long)dst) & 15ull) == 0);
    if (vec_ok) {
        int E4 = E / 4;
        k_count_v4<<<(E4 + T - 1) / T, T>>>((const int4*)dst, E4);
    } else {
        k_count_sc<<<(E + T - 1) / T, T>>>(dst, E);
    }

    k_prep<<<(n + T - 1) / T, T>>>(x, n);

    k_scatter16h<<<(E + T - 1) / T, T>>>(src, dst, E);

    k_transform<<<(n + 255) / 256, 512>>>(W1, b1, W2, n);

    long long w2 = (long long)E * 4;
    k_scatter32h<<<(unsigned)((w2 + T - 1) / T), T>>>(src, dst, E);

    k_final<<<(n + T - 1) / T, T>>>(b2, Wc, bc, out, n);
}

// round 14
// speedup vs baseline: 1.3556x; 1.0654x over previous
#include <cuda_runtime.h>
#include <cuda_fp16.h>

// FakeReviewGNN: 2-layer GCN, N=100000, 7 -> 64 -> 32 -> 2.
// CSR-free scatter pipeline, fp16 scatters, HMMA transform, PDL overlap:
//   k_count     : dst histogram (cnt pre-zeroed / reset by k_final)
//   k_prep      : dinv = rsqrt(cnt+1); xdh = x*dinv (8 halves); ph init
//   k_scatter16h: ph[dst] += xdh[src]          (1 x red.v4.f16x2 / edge)
//   k_transform : persistent (grid=152), weights staged once, tile loop
//   k_scatter32h: s2h[dst] += g2h[src]         (4 threads/edge, coalesced)
//   k_final     : h2 = relu(dinv*s2+b2); log_softmax(h2@Wc+bc); reset cnt
// Dependent kernels use programmatic dependent launch: independent loads
// before cudaGridDependencySynchronize(), so ramps overlap predecessor drains.

#define MAXN 100000
#define F1 64
#define F2 32
#define TF_GRID 152

__device__ int   d_cnt [MAXN];          // zero-init; k_final resets after use
__device__ float d_dinv[MAXN];
__device__ __align__(128) __half d_xdh[MAXN * 8];
__device__ __align__(128) __half d_ph [MAXN * 8];
__device__ __align__(128) __half d_g2h[MAXN * F2];
__device__ __align__(128) __half d_s2h[MAXN * F2];

__device__ __forceinline__ void red_add_v4h2(uint4* addr, uint4 v) {
    asm volatile("red.global.add.noftz.v4.f16x2 [%0], {%1, %2, %3, %4};"
                 :: "l"(addr), "r"(v.x), "r"(v.y), "r"(v.z), "r"(v.w)
                 : "memory");
}

__device__ __forceinline__ unsigned smem_u32(const void* p) {
    return (unsigned)__cvta_generic_to_shared(p);
}

// ---- histogram (cnt assumed zero on entry); first node, no PDL -------------

__global__ void k_count_v4(const int4* __restrict__ dst4, int E4) {
    int i = blockIdx.x * blockDim.x + threadIdx.x;
    if (i >= E4) return;
    int4 d = dst4[i];
    atomicAdd(&d_cnt[d.x], 1);
    atomicAdd(&d_cnt[d.y], 1);
    atomicAdd(&d_cnt[d.z], 1);
    atomicAdd(&d_cnt[d.w], 1);
}

__global__ void k_count_sc(const int* __restrict__ dst, int E) {
    int i = blockIdx.x * blockDim.x + threadIdx.x;
    if (i < E) atomicAdd(&d_cnt[dst[i]], 1);
}

// ---- prep: dinv, xdh = x*dinv as fp16 (pad 7->8), ph init = xdh ------------

__global__ void k_prep(const float* __restrict__ x, int n) {
    int i = blockIdx.x * blockDim.x + threadIdx.x;
    if (i >= n) return;
    const float* xi = x + (long long)i * 7;
    float x0 = xi[0], x1 = xi[1], x2 = xi[2], x3 = xi[3];
    float x4 = xi[4], x5 = xi[5], x6 = xi[6];       // independent of count
    cudaGridDependencySynchronize();                 // wait: d_cnt ready
    float dv = rsqrtf((float)(d_cnt[i] + 1));        // +1 self loop
    d_dinv[i] = dv;
    __half2 h0 = __floats2half2_rn(x0 * dv, x1 * dv);
    __half2 h1 = __floats2half2_rn(x2 * dv, x3 * dv);
    __half2 h2 = __floats2half2_rn(x4 * dv, x5 * dv);
    __half2 h3 = __floats2half2_rn(x6 * dv, 0.0f);
    uint4 v;
    v.x = *reinterpret_cast<unsigned*>(&h0);
    v.y = *reinterpret_cast<unsigned*>(&h1);
    v.z = *reinterpret_cast<unsigned*>(&h2);
    v.w = *reinterpret_cast<unsigned*>(&h3);
    reinterpret_cast<uint4*>(d_xdh)[i] = v;
    reinterpret_cast<uint4*>(d_ph )[i] = v;
}

// ---- layer-1 scatter: ph[dst] += xdh[src], 1 red.v4.f16x2 / edge -----------

__global__ void k_scatter16h(const int* __restrict__ src,
                             const int* __restrict__ dst, int E) {
    int e = blockIdx.x * blockDim.x + threadIdx.x;
    if (e >= E) return;
    int u = src[e], v = dst[e];                      // independent index loads
    cudaGridDependencySynchronize();                 // wait: xdh/ph ready
    uint4 val = reinterpret_cast<const uint4*>(d_xdh)[u];
    red_add_v4h2(&reinterpret_cast<uint4*>(d_ph)[v], val);
}

// ---- persistent tensor-core transform: grid=152, tile loop -----------------
// 512 threads = 16 warps; 16 nodes/warp; 256 nodes/tile.

__global__ void __launch_bounds__(512) k_transform(const float* __restrict__ W1,
                                                   const float* __restrict__ b1,
                                                   const float* __restrict__ W2,
                                                   int n) {
    __shared__ __half W1h[8][F1];        // k-padded fp16 W1, 1 KB
    __shared__ __half W2h[F1][F2];       // fp16 W2, 4 KB
    __shared__ float  b1s[F1];
    __shared__ __half ph_s[256][8];      // 4 KB
    __shared__ float  dinv_s[256];

    int tid = threadIdx.x;
    // ---- independent prelude: stage weights (inputs, not prior output) ----
    for (int i = tid; i < 8 * F1; i += 512) {
        int k = i >> 6, c = i & 63;
        W1h[k][c] = __float2half((k < 7) ? W1[k * F1 + c] : 0.0f);
    }
    for (int i = tid; i < F1 * F2; i += 512)
        W2h[i >> 5][i & 31] = __float2half(W2[i]);
    if (tid < F1) b1s[tid] = b1[tid];
    __syncthreads();

    int warp = tid >> 5;
    int lane = tid & 31;
    int r0   = warp * 16;

    // loop-invariant B fragments for phase 1 (W1)
    unsigned bw1[8];
    {
        int k  = lane & 7;
        int t4 = (lane >> 3) & 3;
        unsigned ad0 = smem_u32(&W1h[k][t4 * 8]);
        unsigned ad1 = smem_u32(&W1h[k][32 + t4 * 8]);
        asm volatile("ldmatrix.sync.aligned.m8n8.x4.trans.shared.b16 {%0,%1,%2,%3}, [%4];"
                     : "=r"(bw1[0]), "=r"(bw1[1]), "=r"(bw1[2]), "=r"(bw1[3])
                     : "r"(ad0));
        asm volatile("ldmatrix.sync.aligned.m8n8.x4.trans.shared.b16 {%0,%1,%2,%3}, [%4];"
                     : "=r"(bw1[4]), "=r"(bw1[5]), "=r"(bw1[6]), "=r"(bw1[7])
                     : "r"(ad1));
    }
    // loop-invariant B fragments for phase 2 (W2)
    unsigned bw2[4][4][2];
    #pragma unroll
    for (int kk = 0; kk < 4; kk++)
        #pragma unroll
        for (int nn = 0; nn < 4; nn++) {
            unsigned addr = smem_u32(&W2h[kk * 16 + (lane & 15)][nn * 8]);
            asm volatile("ldmatrix.sync.aligned.m8n8.x2.trans.shared.b16 {%0,%1}, [%2];"
                         : "=r"(bw2[kk][nn][0]), "=r"(bw2[kk][nn][1]) : "r"(addr));
        }

    int g  = lane >> 2;
    int tc = (lane & 3) * 2;
    int ntiles = (n + 255) / 256;

    cudaGridDependencySynchronize();                 // wait: ph accumulated

    for (int t = blockIdx.x; t < ntiles; t += gridDim.x) {
        int blockbase = t * 256;
        __syncthreads();                             // ph_s reuse guard
        if (tid < 256) {
            int node = blockbase + tid; if (node >= n) node = n - 1;
            *reinterpret_cast<uint4*>(&ph_s[tid][0]) =
                reinterpret_cast<const uint4*>(d_ph)[node];
            dinv_s[tid] = d_dinv[node];
        }
        __syncthreads();

        // phase 1: C1[16x64] = P[16x8] @ W1h[8x64]
        unsigned a0, a1;
        {
            unsigned addr = smem_u32(&ph_s[r0 + (lane & 15)][0]);
            asm volatile("ldmatrix.sync.aligned.m8n8.x2.shared.b16 {%0,%1}, [%2];"
                         : "=r"(a0), "=r"(a1) : "r"(addr));
        }
        float c1[8][4];
        #pragma unroll
        for (int nn = 0; nn < 8; nn++) {
            c1[nn][0] = c1[nn][1] = c1[nn][2] = c1[nn][3] = 0.0f;
            asm volatile(
                "mma.sync.aligned.m16n8k8.row.col.f32.f16.f16.f32 "
                "{%0,%1,%2,%3}, {%4,%5}, {%6}, {%0,%1,%2,%3};"
                : "+f"(c1[nn][0]), "+f"(c1[nn][1]), "+f"(c1[nn][2]), "+f"(c1[nn][3])
                : "r"(a0), "r"(a1), "r"(bw1[nn]));
        }

        // epilogue 1: h1 = relu(dv*c1 + b1) -> phase-2 A fragments
        float dv0 = dinv_s[r0 + g];
        float dv1 = dinv_s[r0 + 8 + g];
        unsigned a2f[4][4];
        #pragma unroll
        for (int nn = 0; nn < 8; nn++) {
            int col = nn * 8 + tc;
            float h0 = fmaxf(dv0 * c1[nn][0] + b1s[col],     0.0f);
            float h1 = fmaxf(dv0 * c1[nn][1] + b1s[col + 1], 0.0f);
            float h2 = fmaxf(dv1 * c1[nn][2] + b1s[col],     0.0f);
            float h3 = fmaxf(dv1 * c1[nn][3] + b1s[col + 1], 0.0f);
            __half2 p01 = __floats2half2_rn(h0, h1);
            __half2 p23 = __floats2half2_rn(h2, h3);
            int kk = nn >> 1, hi = nn & 1;
            a2f[kk][hi * 2]     = *reinterpret_cast<unsigned*>(&p01);
            a2f[kk][hi * 2 + 1] = *reinterpret_cast<unsigned*>(&p23);
        }

        // phase 2: C2[16x32] = H1[16x64] @ W2h[64x32]
        float c2[4][4];
        #pragma unroll
        for (int nn = 0; nn < 4; nn++)
            c2[nn][0] = c2[nn][1] = c2[nn][2] = c2[nn][3] = 0.0f;
        #pragma unroll
        for (int kk = 0; kk < 4; kk++)
            #pragma unroll
            for (int nn = 0; nn < 4; nn++)
                asm volatile(
                    "mma.sync.aligned.m16n8k16.row.col.f32.f16.f16.f32 "
                    "{%0,%1,%2,%3}, {%4,%5,%6,%7}, {%8,%9}, {%0,%1,%2,%3};"
                    : "+f"(c2[nn][0]), "+f"(c2[nn][1]), "+f"(c2[nn][2]), "+f"(c2[nn][3])
                    : "r"(a2f[kk][0]), "r"(a2f[kk][1]), "r"(a2f[kk][2]), "r"(a2f[kk][3]),
                      "r"(bw2[kk][nn][0]), "r"(bw2[kk][nn][1]));

        // epilogue 2: g2 = c2 * dinv -> fp16 store (g2h and s2h)
        int node0 = blockbase + r0 + g;
        int node1 = node0 + 8;
        #pragma unroll
        for (int nn = 0; nn < 4; nn++) {
            int col = nn * 8 + tc;
            __half2 v0 = __floats2half2_rn(c2[nn][0] * dv0, c2[nn][1] * dv0);
            __half2 v1 = __floats2half2_rn(c2[nn][2] * dv1, c2[nn][3] * dv1);
            if (node0 < n) {
                *reinterpret_cast<__half2*>(&d_g2h[(node0 << 5) + col]) = v0;
                *reinterpret_cast<__half2*>(&d_s2h[(node0 << 5) + col]) = v0;
            }
            if (node1 < n) {
                *reinterpret_cast<__half2*>(&d_g2h[(node1 << 5) + col]) = v1;
                *reinterpret_cast<__half2*>(&d_s2h[(node1 << 5) + col]) = v1;
            }
        }
    }
}

// ---- layer-2 scatter: 4 threads/edge (coalesced), 4 red.v4.f16x2 / edge ----

__global__ void k_scatter32h(const int* __restrict__ src,
                             const int* __restrict__ dst, int E) {
    long long idx = (long long)blockIdx.x * blockDim.x + threadIdx.x;
    int e = (int)(idx >> 2);
    int c = (int)(idx & 3);
    if (e >= E) return;
    int u = src[e], v = dst[e];                      // independent index loads
    cudaGridDependencySynchronize();                 // wait: g2h/s2h ready
    uint4 val = reinterpret_cast<const uint4*>(d_g2h)[(long long)u * 4 + c];
    red_add_v4h2(&reinterpret_cast<uint4*>(d_s2h)[(long long)v * 4 + c], val);
}

// ---- final: relu + classifier + log_softmax + cnt reset (thread/node) ------

__global__ void k_final(const float* __restrict__ b2,
                        const float* __restrict__ Wc,
                        const float* __restrict__ bc,
                        float* __restrict__ out, int n) {
    int node = blockIdx.x * blockDim.x + threadIdx.x;
    if (node >= n) return;
    float c0 = bc[0], c1 = bc[1];                    // independent tiny loads
    cudaGridDependencySynchronize();                 // wait: s2h accumulated

    float dv = d_dinv[node];
    const uint4* s4 = reinterpret_cast<const uint4*>(d_s2h) + (long long)node * 4;
    float l0 = c0, l1 = c1;

    #pragma unroll
    for (int j = 0; j < 4; j++) {
        uint4 q = s4[j];
        unsigned w[4] = {q.x, q.y, q.z, q.w};
        #pragma unroll
        for (int t = 0; t < 4; t++) {
            float2 v = __half22float2(*reinterpret_cast<const __half2*>(&w[t]));
            int k = j * 8 + t * 2;
            float h0 = fmaxf(dv * v.x + b2[k],     0.0f);
            float h1 = fmaxf(dv * v.y + b2[k + 1], 0.0f);
            l0 += h0 * Wc[k * 2]     + h1 * Wc[k * 2 + 2];
            l1 += h0 * Wc[k * 2 + 1] + h1 * Wc[k * 2 + 3];
        }
    }

    float m   = fmaxf(l0, l1);
    float lse = m + logf(expf(l0 - m) + expf(l1 - m));
    out[(long long)node * 2]     = l0 - lse;
    out[(long long)node * 2 + 1] = l1 - lse;
    d_cnt[node] = 0;   // reset histogram for next replay (deterministic)
}

// ---- launch (PDL on dependent kernels) -------------------------------------

template <typename F, typename... Args>
static inline void launch_pdl(F kern, dim3 grid, dim3 block, Args... args) {
    cudaLaunchConfig_t cfg = {};
    cfg.gridDim = grid;
    cfg.blockDim = block;
    cfg.dynamicSmemBytes = 0;
    cfg.stream = 0;
    cudaLaunchAttribute at[1];
    at[0].id = cudaLaunchAttributeProgrammaticStreamSerialization;
    at[0].val.programmaticStreamSerializationAllowed = 1;
    cfg.attrs = at;
    cfg.numAttrs = 1;
    cudaLaunchKernelEx(&cfg, kern, args...);
}

extern "C" void kernel_launch(void* const* d_in, const int* in_sizes, int n_in,
                              void* d_out, int out_size) {
    const float* x  = (const float*)d_in[0];
    const int*   ei = (const int*)  d_in[1];
    const float* W1 = (const float*)d_in[2];
    const float* b1 = (const float*)d_in[3];
    const float* W2 = (const float*)d_in[4];
    const float* b2 = (const float*)d_in[5];
    const float* Wc = (const float*)d_in[6];
    const float* bc = (const float*)d_in[7];
    float* out = (float*)d_out;

    int n = in_sizes[0] / 7;     // 100000
    int E = in_sizes[1] / 2;     // 1600000
    const int* src = ei;
    const int* dst = ei + E;

    const int T = 256;

    bool vec_ok = (E % 4 == 0) && ((((unsigned long long)dst) & 15ull) == 0);
    if (vec_ok) {
        int E4 = E / 4;
        k_count_v4<<<(E4 + T - 1) / T, T>>>((const int4*)dst, E4);
    } else {
        k_count_sc<<<(E + T - 1) / T, T>>>(dst, E);
    }

    launch_pdl(k_prep, dim3((n + T - 1) / T), dim3(T), x, n);

    launch_pdl(k_scatter16h, dim3((E + T - 1) / T), dim3(T), src, dst, E);

    launch_pdl(k_transform, dim3(TF_GRID), dim3(512), W1, b1, W2, n);

    long long w2 = (long long)E * 4;
    launch_pdl(k_scatter32h, dim3((unsigned)((w2 + T - 1) / T)), dim3(T),
               src, dst, E);

    launch_pdl(k_final, dim3((n + T - 1) / T), dim3(T), b2, Wc, bc, out, n);
}